// round 2
// baseline (speedup 1.0000x reference)
#include <cuda_runtime.h>

#define BATCH 8
#define NBOX 1024
#define NCLS 32
#define MAXOUT 300
#define SCORE_THRF 0.5f
#define IOU_THRF 0.5f

// Scratch (no allocation allowed)
__device__ unsigned long long g_cand[BATCH * NCLS * MAXOUT]; // 600 KB
__device__ unsigned short g_orig[BATCH * NCLS * NBOX];       // 512 KB: sorted pos -> orig box idx

__device__ __forceinline__ float decode_score(unsigned int hi) {
    unsigned int ordered = ~hi;
    if (ordered & 0x80000000u) return __uint_as_float(ordered & 0x7FFFFFFFu);
    return __uint_as_float(~ordered);
}

// Exact op-order match with the reference (no fma contraction). max/min/add are
// symmetric so operand order across (i,j) is irrelevant bit-wise.
__device__ __forceinline__ bool iou_gt(float4 a, float aa, float4 b, float ab) {
    float yy1 = fmaxf(a.x, b.x);
    float xx1 = fmaxf(a.y, b.y);
    float yy2 = fminf(a.z, b.z);
    float xx2 = fminf(a.w, b.w);
    float ih = fmaxf(__fsub_rn(yy2, yy1), 0.0f);
    float iw = fmaxf(__fsub_rn(xx2, xx1), 0.0f);
    float inter = __fmul_rn(ih, iw);
    float denom = __fsub_rn(__fadd_rn(aa, ab), inter);
    return __fdiv_rn(inter, denom) > IOU_THRF;
}

// ---------------------------------------------------------------------------
// Fused kernel: per-(batch,class) stable sort (bitonic, smem) + chunked greedy
// NMS (32 boxes/step: warp-parallel diagonal resolve + block-parallel sweep)
// + compaction of kept entries into per-class candidate list (<=300).
// ---------------------------------------------------------------------------
__global__ void __launch_bounds__(1024, 2) sortnms_kernel(
        const float* __restrict__ boxes, const float* __restrict__ scores) {
    __shared__ unsigned long long skey[NBOX]; // 8 KB
    __shared__ float4 sbox[NBOX];             // 16 KB
    __shared__ float sarea[NBOX];             // 4 KB
    __shared__ int skeep[NBOX];               // 4 KB
    __shared__ int s_nvalid;
    __shared__ unsigned int s_ck;
    __shared__ int s_wcnt[32], s_woff[32], s_total;

    int b = blockIdx.x >> 5, c = blockIdx.x & 31;
    int tid = threadIdx.x; // 1024 threads

    // --- build sort keys: (~ordered(score) << 32) | orig_idx, ascending ---
    {
        float v = scores[((size_t)b * NBOX + tid) * NCLS + c];
        unsigned int bits = (v > SCORE_THRF) ? __float_as_uint(v) : 0xFF800000u;
        unsigned int ordered = (bits & 0x80000000u) ? ~bits : (bits | 0x80000000u);
        skey[tid] = ((unsigned long long)(~ordered) << 32) | (unsigned int)tid;
    }
    if (tid == 0) s_nvalid = NBOX;

    // --- bitonic sort, one element per thread ---
    for (int k = 2; k <= NBOX; k <<= 1) {
        for (int j = k >> 1; j > 0; j >>= 1) {
            __syncthreads();
            int ixj = tid ^ j;
            if (ixj > tid) {
                unsigned long long a = skey[tid], bb = skey[ixj];
                bool up = ((tid & k) == 0);
                if ((a > bb) == up) { skey[tid] = bb; skey[ixj] = a; }
            }
        }
    }
    __syncthreads();

    unsigned long long k64 = skey[tid];
    int n = (int)(k64 & 0xFFFFFFFFu);
    float sc = decode_score((unsigned int)(k64 >> 32));
    bool valid = sc > SCORE_THRF;
    g_orig[(size_t)blockIdx.x * NBOX + tid] = (unsigned short)n;

    float4 bx = ((const float4*)boxes)[(size_t)b * NBOX + n];
    float my_area = __fmul_rn(__fsub_rn(bx.z, bx.x), __fsub_rn(bx.w, bx.y));
    sbox[tid] = bx;
    sarea[tid] = my_area;
    skeep[tid] = valid ? 1 : 0;
    bool kept = valid;
    if (!valid) atomicMin(&s_nvalid, tid);
    __syncthreads();
    int nvalid = s_nvalid; // valid entries form a prefix

    // --- chunked greedy NMS: 32 boxes per step ---
    for (int cb = 0; cb < nvalid; cb += 32) {
        // Phase 1: warp 0 resolves the 32x32 diagonal for boxes [cb, cb+32)
        if (tid < 32) {
            int j = cb + tid;
            bool k = (skeep[j] != 0);
            float4 bj = sbox[j];
            float aj = sarea[j];
            // precompute pairwise suppression bits (pipelined, no serial dep)
            unsigned int sup = 0;
            #pragma unroll 1
            for (int t = 0; t < 31; t++) {
                if (tid > t) {
                    if (iou_gt(sbox[cb + t], sarea[cb + t], bj, aj)) sup |= (1u << t);
                }
            }
            // serial greedy resolve: pure ALU + ballot
            #pragma unroll 1
            for (int t = 0; t < 32; t++) {
                unsigned int bal = __ballot_sync(0xffffffffu, k);
                if ((bal >> t) & 1u) {
                    if (k && ((sup >> t) & 1u)) k = false;
                }
            }
            skeep[j] = k ? 1 : 0;
            unsigned int ck = __ballot_sync(0xffffffffu, k);
            if (tid == 0) s_ck = ck;
        }
        __syncthreads();
        // Phase 2: parallel sweep — every later still-kept box vs kept chunk boxes
        if (kept && tid >= cb + 32) {
            unsigned int cm = s_ck;
            while (cm) {
                int t = __ffs(cm) - 1;
                cm &= cm - 1;
                if (iou_gt(sbox[cb + t], sarea[cb + t], bx, my_area)) {
                    kept = false;
                    skeep[tid] = 0;
                    break;
                }
            }
        }
        __syncthreads();
    }

    // --- compaction (order-preserving -> candidate list stays key-ascending) ---
    bool fin = (skeep[tid] != 0);
    int lane = tid & 31, wid = tid >> 5;
    unsigned int mask = __ballot_sync(0xffffffffu, fin);
    if (lane == 0) s_wcnt[wid] = __popc(mask);
    __syncthreads();
    if (tid == 0) {
        int acc = 0;
        for (int w = 0; w < 32; w++) { s_woff[w] = acc; acc += s_wcnt[w]; }
        s_total = acc;
    }
    __syncthreads();
    int rank = s_woff[wid] + __popc(mask & ((1u << lane) - 1u));

    unsigned long long* cp = g_cand + (size_t)blockIdx.x * MAXOUT;
    if (fin && rank < MAXOUT) {
        // global key: score bits, low word = class-major flatten index c*N+pos
        cp[rank] = (k64 & 0xFFFFFFFF00000000ull) | (unsigned int)(c * NBOX + tid);
    }
    int total = s_total;
    if (tid >= total && tid < MAXOUT) cp[tid] = 0xFFFFFFFFFFFFFFFFull; // pad
}

// ---------------------------------------------------------------------------
// Kernel 2: per-batch global top-300 (5 rounds of truncated merge-path merges
// of the 32 sorted candidate lists), dedup by original box index, output
// compaction in ascending box-index order, zero padding.
// ---------------------------------------------------------------------------
__global__ void topk_kernel(const float* __restrict__ boxes, float* __restrict__ out) {
    extern __shared__ unsigned long long sm[]; // A: 9600 + B: 4800 keys
    unsigned long long* A = sm;
    unsigned long long* Bb = sm + NCLS * MAXOUT;
    __shared__ int s_first[NBOX];
    __shared__ int s_wcnt[32], s_woff[32];
    __shared__ int s_np;

    int b = blockIdx.x;
    int tid = threadIdx.x; // 1024 threads

    const unsigned long long* cp = g_cand + (size_t)b * NCLS * MAXOUT;
    for (int i = tid; i < NCLS * MAXOUT; i += blockDim.x) A[i] = cp[i];
    for (int i = tid; i < NBOX; i += blockDim.x) s_first[i] = 0x7FFFFFFF;
    __syncthreads();

    unsigned long long* src = A;
    unsigned long long* dst = Bb;
    int nl = NCLS;
    while (nl > 1) {
        int nout = (nl >> 1) * MAXOUT;
        for (int p = tid; p < nout; p += blockDim.x) {
            int m = p / MAXOUT, off = p % MAXOUT;
            const unsigned long long* La = src + (size_t)(2 * m) * MAXOUT;
            const unsigned long long* Lb = src + (size_t)(2 * m + 1) * MAXOUT;
            // merge-path: off-th smallest of La ∪ Lb (keys globally unique)
            int lo = 0, hi = off;
            while (lo < hi) {
                int a = (lo + hi) >> 1;
                if (La[a] < Lb[off - 1 - a]) lo = a + 1; else hi = a;
            }
            int a = lo, bi = off - a;
            unsigned long long va = La[a], vb = Lb[bi];
            dst[(size_t)m * MAXOUT + off] = va < vb ? va : vb;
        }
        __syncthreads();
        unsigned long long* t = src; src = dst; dst = t;
        nl >>= 1;
    }
    const unsigned long long* T = src; // top-300, key-ascending = score-descending

    // dedup: first (best) top-300 position per original box index
    if (tid < MAXOUT) {
        unsigned long long k64 = T[tid];
        float sc = decode_score((unsigned int)(k64 >> 32));
        if (sc > SCORE_THRF) { // padding decodes to NaN -> skipped
            int flat = (int)(k64 & 0xFFFFFFFFu);
            int cc = flat >> 10, pos = flat & 1023;
            int orig = (int)g_orig[((size_t)b * NCLS + cc) * NBOX + pos];
            atomicMin(&s_first[orig], tid);
        }
    }
    __syncthreads();

    bool present = (s_first[tid] < 0x7FFFFFFF);
    int lane = tid & 31, wid = tid >> 5;
    unsigned int mask = __ballot_sync(0xffffffffu, present);
    if (lane == 0) s_wcnt[wid] = __popc(mask);
    __syncthreads();
    if (tid == 0) {
        int acc = 0;
        for (int w = 0; w < 32; w++) { s_woff[w] = acc; acc += s_wcnt[w]; }
        s_np = acc;
    }
    __syncthreads();
    int row = s_woff[wid] + __popc(mask & ((1u << lane) - 1u));

    float* ob = out;                              // [8,300,4]
    float* os = out + (size_t)BATCH * MAXOUT * 4; // [8,300]
    float* oc = os + (size_t)BATCH * MAXOUT;      // [8,300] classes as float

    if (present) {
        int p = s_first[tid];
        unsigned long long k64 = T[p];
        float sc = decode_score((unsigned int)(k64 >> 32));
        int flat = (int)(k64 & 0xFFFFFFFFu);
        int cc = flat >> 10;
        float4 bxv = ((const float4*)boxes)[(size_t)b * NBOX + tid]; // original coords
        ((float4*)ob)[(size_t)b * MAXOUT + row] = bxv;
        os[(size_t)b * MAXOUT + row] = sc;
        oc[(size_t)b * MAXOUT + row] = (float)cc;
    }
    int np = s_np;
    if (tid >= np && tid < MAXOUT) {
        ((float4*)ob)[(size_t)b * MAXOUT + tid] = make_float4(0.f, 0.f, 0.f, 0.f);
        os[(size_t)b * MAXOUT + tid] = 0.f;
        oc[(size_t)b * MAXOUT + tid] = 0.f;
    }
}

// ---------------------------------------------------------------------------
extern "C" void kernel_launch(void* const* d_in, const int* in_sizes, int n_in,
                              void* d_out, int out_size) {
    const float* boxes  = (const float*)d_in[0];
    const float* scores = (const float*)d_in[1];
    if (n_in >= 2 && in_sizes[0] == BATCH * NBOX * NCLS && in_sizes[1] == BATCH * NBOX * 4) {
        scores = (const float*)d_in[0];
        boxes  = (const float*)d_in[1];
    }
    float* out = (float*)d_out;

    size_t topk_smem = (size_t)(NCLS * MAXOUT + (NCLS / 2) * MAXOUT) * sizeof(unsigned long long);
    cudaFuncSetAttribute(topk_kernel, cudaFuncAttributeMaxDynamicSharedMemorySize, (int)topk_smem);

    sortnms_kernel<<<BATCH * NCLS, NBOX>>>(boxes, scores);
    topk_kernel<<<BATCH, NBOX, topk_smem>>>(boxes, out);
}

// round 3
// speedup vs baseline: 2.1457x; 2.1457x over previous
#include <cuda_runtime.h>

#define BATCH 8
#define NBOX 1024
#define NCLS 32
#define MAXOUT 300
#define SCORE_THRF 0.5f
#define IOU_THRF 0.5f

// Scratch (no allocation allowed)
__device__ unsigned long long g_cand[BATCH * NCLS * MAXOUT]; // 600 KB
__device__ unsigned short g_orig[BATCH * NCLS * NBOX];       // 512 KB: sorted pos -> orig idx

__device__ __forceinline__ float decode_score(unsigned int hi) {
    unsigned int ordered = ~hi;
    if (ordered & 0x80000000u) return __uint_as_float(ordered & 0x7FFFFFFFu);
    return __uint_as_float(~ordered);
}

// Exact-rounding suppression test matching the reference op order. The quick
// reject (yy2>yy1 && xx2>xx1) is bit-exact: if it fails, inter==0 -> iou==0,
// never > 0.5 (areas are strictly positive, no div-by-zero on the taken path).
__device__ __forceinline__ bool sup_test(float4 a, float aa, float4 b, float ab) {
    float yy1 = fmaxf(a.x, b.x);
    float xx1 = fmaxf(a.y, b.y);
    float yy2 = fminf(a.z, b.z);
    float xx2 = fminf(a.w, b.w);
    if (!(yy2 > yy1 && xx2 > xx1)) return false;
    float ih = __fsub_rn(yy2, yy1);
    float iw = __fsub_rn(xx2, xx1);
    float inter = __fmul_rn(ih, iw);
    float denom = __fsub_rn(__fadd_rn(aa, ab), inter);
    return __fdiv_rn(inter, denom) > IOU_THRF;
}

// ---------------------------------------------------------------------------
// Fused: per-(batch,class) stable sort (hybrid shfl/smem bitonic) + chunked
// greedy NMS with quick-reject IoU and sparse diagonal resolve + compaction.
// ---------------------------------------------------------------------------
__global__ void __launch_bounds__(1024, 2) sortnms_kernel(
        const float* __restrict__ boxes, const float* __restrict__ scores) {
    __shared__ unsigned long long skey[NBOX]; // 8 KB (sort only)
    __shared__ float4 sbox[NBOX];             // 16 KB
    __shared__ float sarea[NBOX];             // 4 KB
    __shared__ unsigned int s_ck[NBOX / 32];  // kept-bits per chunk
    __shared__ int s_wcnt[32], s_woff[32], s_total;

    int tid = threadIdx.x, lane = tid & 31, wid = tid >> 5;
    int b = blockIdx.x >> 5, c = blockIdx.x & 31;

    // --- sort key: (~ordered(score)<<32) | orig_idx, ascending = score desc ---
    unsigned long long key;
    {
        float v = scores[((size_t)b * NBOX + tid) * NCLS + c];
        unsigned int bits = (v > SCORE_THRF) ? __float_as_uint(v) : 0xFF800000u;
        unsigned int ordered = (bits & 0x80000000u) ? ~bits : (bits | 0x80000000u);
        key = ((unsigned long long)(~ordered) << 32) | (unsigned int)tid;
    }

    // --- hybrid bitonic sort, one element per thread (register-resident) ---
    for (int k = 2; k <= NBOX; k <<= 1) {
        bool up = ((tid & k) == 0);
        for (int j = k >> 1; j > 0; j >>= 1) {
            bool lower = ((tid & j) == 0);
            bool takeMin = (lower == up);
            unsigned long long p;
            if (j >= 32) {
                skey[tid] = key;
                __syncthreads();
                p = skey[tid ^ j];
                __syncthreads();
            } else {
                p = __shfl_xor_sync(0xffffffffu, key, j);
            }
            key = takeMin ? (key < p ? key : p) : (key > p ? key : p);
        }
    }

    // --- post-sort setup ---
    int n = (int)(key & 0xFFFFFFFFu);
    bool valid = ((unsigned int)(key >> 32) != 0xFF800000u); // -inf marker = invalid
    g_orig[(size_t)blockIdx.x * NBOX + tid] = (unsigned short)n;

    float4 bx = ((const float4*)boxes)[(size_t)b * NBOX + n];
    float area = __fmul_rn(__fsub_rn(bx.z, bx.x), __fsub_rn(bx.w, bx.y));
    sbox[tid] = bx;
    sarea[tid] = area;
    int nvalid = __syncthreads_count(valid); // valid entries form a prefix
    bool kept = valid;

    // --- chunked greedy NMS, one barrier per 32-box chunk ---
    for (int cb = 0; cb < nvalid; cb += 32) {
        int wc = cb >> 5;
        if (wid == wc) {
            // Diagonal: this warp owns boxes [cb, cb+32); kept is register-local.
            bool k = kept;
            unsigned int rowmask = 0; // earlier chunk lanes that would suppress me
            if (k) {
                for (int t = 0; t < lane; t++) {
                    if (sup_test(sbox[cb + t], sarea[cb + t], bx, area))
                        rowmask |= (1u << t);
                }
            }
            // serial resolve only over lanes that suppress anyone (sparse)
            unsigned int um = __reduce_or_sync(0xffffffffu, rowmask);
            while (um) {
                int t = __ffs(um) - 1;
                um &= um - 1;
                unsigned int bal = __ballot_sync(0xffffffffu, k);
                if (((bal >> t) & 1u) && ((rowmask >> t) & 1u)) k = false;
            }
            kept = k;
            unsigned int ck = __ballot_sync(0xffffffffu, k);
            if (lane == 0) s_ck[wc] = ck;
        }
        __syncthreads();
        // Sweep: later still-kept boxes vs this chunk's kept boxes
        if (wid > wc && kept) {
            unsigned int cm = s_ck[wc];
            while (cm) {
                int t = __ffs(cm) - 1;
                cm &= cm - 1;
                if (sup_test(sbox[cb + t], sarea[cb + t], bx, area)) {
                    kept = false;
                    break;
                }
            }
        }
    }
    __syncthreads();

    // --- order-preserving compaction into per-class candidate list ---
    unsigned int mask = __ballot_sync(0xffffffffu, kept);
    if (lane == 0) s_wcnt[wid] = __popc(mask);
    __syncthreads();
    if (tid == 0) {
        int acc = 0;
        for (int w = 0; w < 32; w++) { s_woff[w] = acc; acc += s_wcnt[w]; }
        s_total = acc;
    }
    __syncthreads();
    int rank = s_woff[wid] + __popc(mask & ((1u << lane) - 1u));

    unsigned long long* cp = g_cand + (size_t)blockIdx.x * MAXOUT;
    if (kept && rank < MAXOUT) {
        // global key: score bits, low word = class-major flatten index c*N+pos
        cp[rank] = (key & 0xFFFFFFFF00000000ull) | (unsigned int)(c * NBOX + tid);
    }
    int total = s_total;
    if (tid >= total && tid < MAXOUT) cp[tid] = 0xFFFFFFFFFFFFFFFFull; // pad
}

// ---------------------------------------------------------------------------
// Kernel 2: per-batch global top-300 (truncated merge-path merge tree of the
// 32 sorted candidate lists), dedup by original box index, output compaction
// in ascending box-index order, zero padding.  (Unchanged from passing R1/R2.)
// ---------------------------------------------------------------------------
__global__ void topk_kernel(const float* __restrict__ boxes, float* __restrict__ out) {
    extern __shared__ unsigned long long sm[]; // A: 9600 + B: 4800 keys
    unsigned long long* A = sm;
    unsigned long long* Bb = sm + NCLS * MAXOUT;
    __shared__ int s_first[NBOX];
    __shared__ int s_wcnt[32], s_woff[32];
    __shared__ int s_np;

    int b = blockIdx.x;
    int tid = threadIdx.x; // 1024 threads

    const unsigned long long* cp = g_cand + (size_t)b * NCLS * MAXOUT;
    for (int i = tid; i < NCLS * MAXOUT; i += blockDim.x) A[i] = cp[i];
    for (int i = tid; i < NBOX; i += blockDim.x) s_first[i] = 0x7FFFFFFF;
    __syncthreads();

    unsigned long long* src = A;
    unsigned long long* dst = Bb;
    int nl = NCLS;
    while (nl > 1) {
        int nout = (nl >> 1) * MAXOUT;
        for (int p = tid; p < nout; p += blockDim.x) {
            int m = p / MAXOUT, off = p % MAXOUT;
            const unsigned long long* La = src + (size_t)(2 * m) * MAXOUT;
            const unsigned long long* Lb = src + (size_t)(2 * m + 1) * MAXOUT;
            int lo = 0, hi = off;
            while (lo < hi) {
                int a = (lo + hi) >> 1;
                if (La[a] < Lb[off - 1 - a]) lo = a + 1; else hi = a;
            }
            int a = lo, bi = off - a;
            unsigned long long va = La[a], vb = Lb[bi];
            dst[(size_t)m * MAXOUT + off] = va < vb ? va : vb;
        }
        __syncthreads();
        unsigned long long* t = src; src = dst; dst = t;
        nl >>= 1;
    }
    const unsigned long long* T = src; // top-300, key-ascending = score-descending

    if (tid < MAXOUT) {
        unsigned long long k64 = T[tid];
        float sc = decode_score((unsigned int)(k64 >> 32));
        if (sc > SCORE_THRF) { // padding decodes invalid -> skipped
            int flat = (int)(k64 & 0xFFFFFFFFu);
            int cc = flat >> 10, pos = flat & 1023;
            int orig = (int)g_orig[((size_t)b * NCLS + cc) * NBOX + pos];
            atomicMin(&s_first[orig], tid);
        }
    }
    __syncthreads();

    bool present = (s_first[tid] < 0x7FFFFFFF);
    int lane = tid & 31, wid = tid >> 5;
    unsigned int mask = __ballot_sync(0xffffffffu, present);
    if (lane == 0) s_wcnt[wid] = __popc(mask);
    __syncthreads();
    if (tid == 0) {
        int acc = 0;
        for (int w = 0; w < 32; w++) { s_woff[w] = acc; acc += s_wcnt[w]; }
        s_np = acc;
    }
    __syncthreads();
    int row = s_woff[wid] + __popc(mask & ((1u << lane) - 1u));

    float* ob = out;                              // [8,300,4]
    float* os = out + (size_t)BATCH * MAXOUT * 4; // [8,300]
    float* oc = os + (size_t)BATCH * MAXOUT;      // [8,300] classes as float

    if (present) {
        int p = s_first[tid];
        unsigned long long k64 = T[p];
        float sc = decode_score((unsigned int)(k64 >> 32));
        int flat = (int)(k64 & 0xFFFFFFFFu);
        int cc = flat >> 10;
        float4 bxv = ((const float4*)boxes)[(size_t)b * NBOX + tid]; // original coords
        ((float4*)ob)[(size_t)b * MAXOUT + row] = bxv;
        os[(size_t)b * MAXOUT + row] = sc;
        oc[(size_t)b * MAXOUT + row] = (float)cc;
    }
    int np = s_np;
    if (tid >= np && tid < MAXOUT) {
        ((float4*)ob)[(size_t)b * MAXOUT + tid] = make_float4(0.f, 0.f, 0.f, 0.f);
        os[(size_t)b * MAXOUT + tid] = 0.f;
        oc[(size_t)b * MAXOUT + tid] = 0.f;
    }
}

// ---------------------------------------------------------------------------
extern "C" void kernel_launch(void* const* d_in, const int* in_sizes, int n_in,
                              void* d_out, int out_size) {
    const float* boxes  = (const float*)d_in[0];
    const float* scores = (const float*)d_in[1];
    if (n_in >= 2 && in_sizes[0] == BATCH * NBOX * NCLS && in_sizes[1] == BATCH * NBOX * 4) {
        scores = (const float*)d_in[0];
        boxes  = (const float*)d_in[1];
    }
    float* out = (float*)d_out;

    size_t topk_smem = (size_t)(NCLS * MAXOUT + (NCLS / 2) * MAXOUT) * sizeof(unsigned long long);
    cudaFuncSetAttribute(topk_kernel, cudaFuncAttributeMaxDynamicSharedMemorySize, (int)topk_smem);

    sortnms_kernel<<<BATCH * NCLS, NBOX>>>(boxes, scores);
    topk_kernel<<<BATCH, NBOX, topk_smem>>>(boxes, out);
}